// round 6
// baseline (speedup 1.0000x reference)
#include <cuda_runtime.h>
#include <cuda_bf16.h>
#include <cuda_fp16.h>
#include <mma.h>
#include <cstdint>

using namespace nvcuda;

#define B_  512
#define T_  256
#define V_  1000
#define E_  256
#define H_  512
#define G_  2048   // 4*H

#define LDW 520    // padded bf16 smem pitch: 1040B, conflict-free for ldmatrix row stepping

// ---------------- fast activations ----------------
__device__ __forceinline__ float tanh_fast(float x) {
    float y; asm("tanh.approx.f32 %0, %1;" : "=f"(y) : "f"(x)); return y;
}
__device__ __forceinline__ float sigmoid_fast(float x) {
    return fmaf(0.5f, tanh_fast(0.5f * x), 0.5f);
}
__device__ __forceinline__ uint32_t smem_u32(const void* p) {
    uint32_t a;
    asm("{ .reg .u64 t; cvta.to.shared.u64 t, %1; cvt.u32.u64 %0, t; }" : "=r"(a) : "l"(p));
    return a;
}
#define LDMATRIX_X4(r0, r1, r2, r3, addr) \
    asm volatile("ldmatrix.sync.aligned.m8n8.x4.shared.b16 {%0,%1,%2,%3}, [%4];" \
        : "=r"(r0), "=r"(r1), "=r"(r2), "=r"(r3) : "r"(addr))
#define MMA_16816(d, a0, a1, a2, a3, b0, b1) \
    asm volatile("mma.sync.aligned.m16n8k16.row.col.f32.bf16.bf16.f32 " \
        "{%0,%1,%2,%3}, {%4,%5,%6,%7}, {%8,%9}, {%0,%1,%2,%3};" \
        : "+f"(d[0]), "+f"(d[1]), "+f"(d[2]), "+f"(d[3]) \
        : "r"(a0), "r"(a1), "r"(a2), "r"(a3), "r"(b0), "r"(b1))

// ---------------- static device scratch ----------------
__device__ __align__(16) __nv_bfloat16 g_H[(T_ + 1)][B_][H_];   // h states (~134MB)
__device__ __align__(16) float          g_tab[V_][G_];          // interleaved [v][4*h+q] (8MB)
__device__ __align__(16) __nv_bfloat16  g_Whh[G_][H_];          // bf16 W_hh1 (2MB)
__device__ __align__(16) __nv_bfloat16  g_Wout[1024][H_];       // bf16 W_out padded (1MB)
__device__ __align__(16) __half         g_logits[T_ * B_][1024];// fp16 logits scratch (268MB)
__device__ __align__(16) short          g_chars[T_][B_];
__device__ int g_cnt[8 * 32];
__device__ volatile int g_rel[8 * 32];

// ---------------- init ----------------
__global__ void init_kernel(const float* __restrict__ Whh1, const float* __restrict__ WoutF,
                            const void* __restrict__ gt_raw) {
    int stride = gridDim.x * blockDim.x;
    int tid0 = blockIdx.x * blockDim.x + threadIdx.x;
    if (tid0 < 8) { g_cnt[tid0 * 32] = 0; g_rel[tid0 * 32] = 0; }
    const int* p = (const int*)gt_raw;
    int z = (p[1] == 0) + (p[3] == 0) + (p[5] == 0) + (p[7] == 0) +
            (p[9] == 0) + (p[11] == 0) + (p[13] == 0) + (p[15] == 0);
    int is64 = (z == 8);
    for (int i = tid0; i < G_ * H_; i += stride) {
        ((__nv_bfloat16*)g_Whh)[i] = __float2bfloat16(Whh1[i]);
        if (i < 1024 * H_) {
            float v = (i < V_ * H_) ? WoutF[i] : 0.f;
            ((__nv_bfloat16*)g_Wout)[i] = __float2bfloat16(v);
        }
        if (i < B_ * H_) ((__nv_bfloat16*)g_H)[i] = __float2bfloat16(0.f);
        if (i < T_ * B_) {
            int t = i / B_, b = i % B_;
            int ch = 0;
            if (t > 0) {
                int idx = b * T_ + (t - 1);
                ch = is64 ? (int)((const long long*)gt_raw)[idx] : ((const int*)gt_raw)[idx];
            }
            ((short*)g_chars)[i] = (short)ch;
        }
    }
}

// ---------------- ih gate table (interleaved [v][4*h+q]) ----------------
__global__ void table_kernel(const float* __restrict__ emb, const float* __restrict__ Wih,
                             const float* __restrict__ bih, const float* __restrict__ bhh) {
    int gtile = blockIdx.x;
    int vtile = blockIdx.y;
    __shared__ float sE[64][65];
    __shared__ float sW[64][65];
    float acc[4][4] = {};
    int tm = threadIdx.x >> 4, tn = threadIdx.x & 15;
    for (int kc = 0; kc < 4; kc++) {
        for (int i = threadIdx.x; i < 64 * 64; i += 256) {
            int r = i >> 6, c = i & 63;
            int v = vtile * 64 + r;
            sE[r][c] = (v < V_) ? emb[v * E_ + kc * 64 + c] : 0.f;
            sW[r][c] = Wih[(gtile * 64 + r) * E_ + kc * 64 + c];
        }
        __syncthreads();
        #pragma unroll 8
        for (int k = 0; k < 64; k++) {
            float e[4], w[4];
            #pragma unroll
            for (int mi = 0; mi < 4; mi++) e[mi] = sE[tm * 4 + mi][k];
            #pragma unroll
            for (int ni = 0; ni < 4; ni++) w[ni] = sW[tn * 4 + ni][k];
            #pragma unroll
            for (int mi = 0; mi < 4; mi++)
                #pragma unroll
                for (int ni = 0; ni < 4; ni++) acc[mi][ni] += e[mi] * w[ni];
        }
        __syncthreads();
    }
    #pragma unroll
    for (int mi = 0; mi < 4; mi++) {
        int v = vtile * 64 + tm * 4 + mi;
        if (v >= V_) continue;
        #pragma unroll
        for (int ni = 0; ni < 4; ni++) {
            int g = gtile * 64 + tn * 4 + ni;            // gate-major index q*512+h
            g_tab[v][(g & 511) * 4 + (g >> 9)] = acc[mi][ni] + bih[g] + bhh[g];
        }
    }
}

// ---------------- persistent recurrence: raw mma + register-resident gates ----------------
// 128 blocks: bt = bid>>4 (8 x 64 batch), gt = bid&15 (16 x 32 h-cols).
// W' interleaved rows n = 4*h_local + q, staged to SMEM once. A (h_t) staged per step.
// Gates stay in mma accumulator registers; one shfl pair merges (i,f)/(g,o).
#define SMEM_RECUR ((128 * LDW + 64 * LDW) * 2)

__global__ __launch_bounds__(256, 1) void recur_kernel() {
    extern __shared__ __nv_bfloat16 smem[];
    __nv_bfloat16* sW = smem;               // 128 x LDW (W' interleaved)
    __nv_bfloat16* sA = smem + 128 * LDW;   // 64 x LDW

    const int gt = blockIdx.x & 15;
    const int bt = blockIdx.x >> 4;
    const int b0 = bt * 64;
    const int tid = threadIdx.x;

    // stage W' once: row n -> g_Whh[(n&3)*512 + gt*32 + (n>>2)]
    for (int i = tid; i < 128 * 64; i += 256) {
        int n = i >> 6, c = i & 63;
        int grow = (n & 3) * H_ + gt * 32 + (n >> 2);
        ((uint4*)(sW + n * LDW))[c] = *(const uint4*)&g_Whh[grow][c * 8];
    }
    __syncthreads();

    const int warp = tid >> 5, lane = tid & 31;
    const int wm = warp >> 2;       // 0..1 : 32 batch rows
    const int wn = warp & 3;        // 0..3 : 32 n-cols (8 h x 4 gates)
    const int g8 = lane >> 2;       // 0..7
    const int t4 = lane & 3;
    const int odd = t4 & 1;
    const int tb2 = t4 >> 1;

    const uint32_t sA32 = smem_u32(sA), sW32 = smem_u32(sW);
    uint32_t aAddr[2], bAddr[2];
    #pragma unroll
    for (int mi = 0; mi < 2; mi++)
        aAddr[mi] = sA32 + (uint32_t)(((wm * 32 + mi * 16 + (lane & 15)) * LDW + (lane >> 4) * 8) * 2);
    #pragma unroll
    for (int nj = 0; nj < 2; nj++)
        bAddr[nj] = sW32 + (uint32_t)(((wn * 32 + nj * 16 + (lane & 15)) * LDW + (lane >> 4) * 8) * 2);

    int bb[2];
    #pragma unroll
    for (int mi = 0; mi < 2; mi++) bb[mi] = b0 + wm * 32 + mi * 16 + g8 + odd * 8;

    // h column handled by this thread for accumulator ni: gt*32 + wn*8 + 2*ni + tb2
    int hc[4];
    #pragma unroll
    for (int ni = 0; ni < 4; ni++) hc[ni] = gt * 32 + wn * 8 + 2 * ni + tb2;

    float creg[2][4];
    #pragma unroll
    for (int mi = 0; mi < 2; mi++)
        #pragma unroll
        for (int ni = 0; ni < 4; ni++) creg[mi][ni] = 0.f;

    for (int t = 0; t < T_; t++) {
        // prefetch gate-table rows (independent of h_t -> hides under staging+GEMM)
        float4 tb[2][4];
        #pragma unroll
        for (int mi = 0; mi < 2; mi++) {
            int ch = g_chars[t][bb[mi]];
            const float4* trow = (const float4*)&g_tab[ch][0];
            #pragma unroll
            for (int ni = 0; ni < 4; ni++)
                tb[mi][ni] = trow[hc[ni]];
        }

        // stage A = h_t [64 x 512]
        for (int i = tid; i < 64 * 64; i += 256) {
            int r = i >> 6, c = i & 63;
            ((uint4*)(sA + r * LDW))[c] = ((const uint4*)&g_H[t][b0 + r][0])[c];
        }
        __syncthreads();

        float acc[2][4][4];
        #pragma unroll
        for (int mi = 0; mi < 2; mi++)
            #pragma unroll
            for (int ni = 0; ni < 4; ni++)
                #pragma unroll
                for (int e = 0; e < 4; e++) acc[mi][ni][e] = 0.f;

        #pragma unroll 8
        for (int kk = 0; kk < 32; kk++) {
            uint32_t a[2][4], bm[2][4];
            #pragma unroll
            for (int mi = 0; mi < 2; mi++)
                LDMATRIX_X4(a[mi][0], a[mi][1], a[mi][2], a[mi][3], aAddr[mi] + kk * 32);
            #pragma unroll
            for (int nj = 0; nj < 2; nj++)
                LDMATRIX_X4(bm[nj][0], bm[nj][1], bm[nj][2], bm[nj][3], bAddr[nj] + kk * 32);
            #pragma unroll
            for (int mi = 0; mi < 2; mi++)
                #pragma unroll
                for (int nj = 0; nj < 2; nj++) {
                    MMA_16816(acc[mi][nj * 2 + 0], a[mi][0], a[mi][1], a[mi][2], a[mi][3],
                              bm[nj][0], bm[nj][2]);
                    MMA_16816(acc[mi][nj * 2 + 1], a[mi][0], a[mi][1], a[mi][2], a[mi][3],
                              bm[nj][1], bm[nj][3]);
                }
        }

        // pointwise: merge gate pairs via shfl, all in registers
        #pragma unroll
        for (int mi = 0; mi < 2; mi++) {
            #pragma unroll
            for (int ni = 0; ni < 4; ni++) {
                float c0 = acc[mi][ni][0], c1 = acc[mi][ni][1];
                float c2 = acc[mi][ni][2], c3 = acc[mi][ni][3];
                float u = odd ? c0 : c2;
                float v = odd ? c1 : c3;
                float ru = __shfl_xor_sync(0xFFFFFFFF, u, 1);
                float rv = __shfl_xor_sync(0xFFFFFFFF, v, 1);
                float gi = odd ? ru : c0;
                float gf = odd ? rv : c1;
                float gg = odd ? c2 : ru;
                float go = odd ? c3 : rv;
                gi = sigmoid_fast(gi + tb[mi][ni].x);
                gf = sigmoid_fast(gf + tb[mi][ni].y);
                gg = tanh_fast(gg + tb[mi][ni].z);
                go = sigmoid_fast(go + tb[mi][ni].w);
                float cv = fmaf(gf, creg[mi][ni], gi * gg);
                creg[mi][ni] = cv;
                float hv = go * tanh_fast(cv);
                g_H[t + 1][bb[mi]][hc[ni]] = __float2bfloat16(hv);
            }
        }

        // per-bt barrier across the 16 gt blocks
        __threadfence();
        __syncthreads();
        if (tid == 0) {
            int v = atomicAdd(&g_cnt[bt * 32], 1);
            if (v == 15) {
                g_cnt[bt * 32] = 0;
                __threadfence();
                atomicExch((int*)&g_rel[bt * 32], t + 1);
            } else {
                while (g_rel[bt * 32] < t + 1) __nanosleep(32);
                __threadfence();
            }
        }
        __syncthreads();
    }
}

// ---------------- batched output projection -> fp16 logits ----------------
// grid (4 x 2048), 256 thr, tile 64m x 256n; dynamic smem: sA(64x72) + sB(256x72) bf16,
// epilogue reuses the same region as a float staging tile (64 x 132).
#define LOGITS_SMEM ((64 * 72 + 256 * 72) * 2)

__global__ __launch_bounds__(256, 2) void logits_kernel() {
    extern __shared__ __nv_bfloat16 lsm[];
    __nv_bfloat16* sA = lsm;
    __nv_bfloat16* sB = lsm + 64 * 72;
    float* sF = (float*)lsm;                 // 64 x 132 floats (33.8KB < 46KB)
    const __nv_bfloat16* A = &g_H[1][0][0];  // [131072][512]

    int nt = blockIdx.x, mt = blockIdx.y;
    int warp = threadIdx.x >> 5;
    int wm = warp >> 2;
    int wn = warp & 3;
    wmma::fragment<wmma::accumulator, 16, 16, 16, float> acc[2][4];
    #pragma unroll
    for (int mi = 0; mi < 2; mi++)
        #pragma unroll
        for (int ni = 0; ni < 4; ni++) wmma::fill_fragment(acc[mi][ni], 0.f);

    for (int kc = 0; kc < 8; kc++) {
        #pragma unroll
        for (int i = threadIdx.x; i < 512; i += 256) {
            int r = i >> 3, c8 = i & 7;
            *(uint4*)(sA + r * 72 + c8 * 8) = *(const uint4*)&A[(mt * 64 + r) * 512 + kc * 64 + c8 * 8];
        }
        #pragma unroll
        for (int i = threadIdx.x; i < 2048; i += 256) {
            int n = i >> 3, c8 = i & 7;
            *(uint4*)(sB + n * 72 + c8 * 8) = *(const uint4*)&g_Wout[nt * 256 + n][kc * 64 + c8 * 8];
        }
        __syncthreads();
        #pragma unroll
        for (int kk = 0; kk < 4; kk++) {
            wmma::fragment<wmma::matrix_a, 16, 16, 16, __nv_bfloat16, wmma::row_major> fa[2];
            #pragma unroll
            for (int mi = 0; mi < 2; mi++)
                wmma::load_matrix_sync(fa[mi], sA + (wm * 32 + mi * 16) * 72 + kk * 16, 72);
            #pragma unroll
            for (int ni = 0; ni < 4; ni++) {
                wmma::fragment<wmma::matrix_b, 16, 16, 16, __nv_bfloat16, wmma::col_major> fb;
                wmma::load_matrix_sync(fb, sB + (wn * 64 + ni * 16) * 72 + kk * 16, 72);
                #pragma unroll
                for (int mi = 0; mi < 2; mi++)
                    wmma::mma_sync(acc[mi][ni], fa[mi], fb, acc[mi][ni]);
            }
        }
        __syncthreads();
    }

    // epilogue: two half-tiles of 128 cols, staged f32 in smem, written as fp16
    #pragma unroll
    for (int p = 0; p < 2; p++) {
        if ((wn >> 1) == p) {
            #pragma unroll
            for (int mi = 0; mi < 2; mi++)
                #pragma unroll
                for (int ni = 0; ni < 4; ni++)
                    wmma::store_matrix_sync(sF + (wm * 32 + mi * 16) * 132 + ((wn & 1) * 64 + ni * 16),
                                            acc[mi][ni], 132, wmma::mem_row_major);
        }
        __syncthreads();
        for (int i = threadIdx.x; i < 64 * 16; i += 256) {
            int r = i >> 4, c8 = (i & 15) * 8;
            const float* src = sF + r * 132 + c8;
            __half h[8];
            #pragma unroll
            for (int e = 0; e < 8; e++) h[e] = __float2half(src[e]);
            *(uint4*)&g_logits[mt * 64 + r][nt * 256 + p * 128 + c8] = *(uint4*)h;
        }
        __syncthreads();
    }
}

// ---------------- log_softmax + bias + remap ----------------
__global__ __launch_bounds__(256, 4) void softmax_kernel(float* __restrict__ out,
                                                         const float* __restrict__ bout) {
    int row = blockIdx.x;
    int t = row >> 9, b = row & 511;
    const __half* lg = g_logits[row];
    __shared__ float red[8];

    int lane = threadIdx.x & 31;
    int warp = threadIdx.x >> 5;

    float v[4];
    float mx = -1e30f;
    #pragma unroll
    for (int j = 0; j < 4; j++) {
        int c = threadIdx.x + j * 256;
        v[j] = (c < V_) ? (__half2float(lg[c]) + bout[c]) : -1e30f;
        mx = fmaxf(mx, v[j]);
    }
    #pragma unroll
    for (int s = 16; s > 0; s >>= 1) mx = fmaxf(mx, __shfl_xor_sync(0xFFFFFFFF, mx, s));
    if (lane == 0) red[warp] = mx;
    __syncthreads();
    float m0 = red[lane & 7];
    #pragma unroll
    for (int s = 4; s > 0; s >>= 1) m0 = fmaxf(m0, __shfl_xor_sync(0xFFFFFFFF, m0, s));
    mx = m0;

    float sum = 0.f;
    #pragma unroll
    for (int j = 0; j < 4; j++) {
        int c = threadIdx.x + j * 256;
        if (c < V_) sum += __expf(v[j] - mx);
    }
    #pragma unroll
    for (int s = 16; s > 0; s >>= 1) sum += __shfl_xor_sync(0xFFFFFFFF, sum, s);
    __syncthreads();
    if (lane == 0) red[warp] = sum;
    __syncthreads();
    float s0 = red[lane & 7];
    #pragma unroll
    for (int s = 4; s > 0; s >>= 1) s0 += __shfl_xor_sync(0xFFFFFFFF, s0, s);
    float lse = mx + logf(s0);

    float* o = out + ((size_t)b * T_ + t) * V_;
    #pragma unroll
    for (int j = 0; j < 4; j++) {
        int c = threadIdx.x + j * 256;
        if (c < V_) o[c] = v[j] - lse;
    }
}

// ---------------- launch ----------------
extern "C" void kernel_launch(void* const* d_in, const int* in_sizes, int n_in,
                              void* d_out, int out_size) {
    const void*  gt   = d_in[1];
    const float* emb  = (const float*)d_in[2];
    const float* Wih1 = (const float*)d_in[7];
    const float* Whh1 = (const float*)d_in[8];
    const float* bih1 = (const float*)d_in[9];
    const float* bhh1 = (const float*)d_in[10];
    const float* Wout = (const float*)d_in[11];
    const float* bout = (const float*)d_in[12];
    float* out = (float*)d_out;

    cudaFuncSetAttribute(recur_kernel, cudaFuncAttributeMaxDynamicSharedMemorySize, SMEM_RECUR);

    init_kernel<<<1024, 256>>>(Whh1, Wout, gt);
    table_kernel<<<dim3(32, 16), 256>>>(emb, Wih1, bih1, bhh1);
    recur_kernel<<<128, 256, SMEM_RECUR>>>();
    logits_kernel<<<dim3(4, 2048), 256, LOGITS_SMEM>>>();
    softmax_kernel<<<T_ * B_, 256>>>(out, bout);
}